// round 14
// baseline (speedup 1.0000x reference)
#include <cuda_runtime.h>
#include <stdint.h>

#define NROWS 10496   // 256*41
#define DIM   512
#define KC    4096
#define NL    8
#define COMMIT 0.25f

#define MT 64
#define KT 128
#define DT 16
#define SPLITS 8
#define KSPLIT (KC/SPLITS)   // 512
#define NKT (KSPLIT/KT)      // 4
#define AST 516              // padded A row stride (floats), 16B-aligned, avoids broadcast conflicts
#define NCHUNK (DIM/DT)      // 32

#define SMEM_FLOATS (MT*AST + 2*DT*KT)   // 33024 + 4096 = 37120
#define SMEM_BYTES  (SMEM_FLOATS*4)      // 148480

// -------- device scratch (no dynamic alloc allowed) --------
__device__ float g_resid[NROWS*DIM];                    // current residual
__device__ float g_esq[NL*KC];                          // ||e||^2 per code
__device__ float g_rowsum[NROWS];                       // ||r||^2 per row (per layer)
__device__ unsigned long long g_part[NROWS*SPLITS];     // packed (distbits<<32 | idx) partial argmins
__device__ int   g_best[NROWS];
__device__ float g_rowloss[NROWS];                      // sum (q-r)^2 per row, across layers

// ---------------- init: residual <- x, zero qout, zero rowloss ----------------
__global__ void init_kernel(const float4* __restrict__ x4, float4* __restrict__ outQ4) {
    int i = blockIdx.x * 256 + threadIdx.x;            // grid covers NROWS*DIM/4 exactly
    float4 v = x4[i];
    ((float4*)g_resid)[i] = v;
    outQ4[i] = make_float4(0.f, 0.f, 0.f, 0.f);
    if (i < NROWS) g_rowloss[i] = 0.f;
}

// ---------------- esq: one warp per code ----------------
__global__ void esq_kernel(const float* __restrict__ cb) {
    int warp = (blockIdx.x * blockDim.x + threadIdx.x) >> 5;
    int lane = threadIdx.x & 31;
    if (warp >= NL * KC) return;
    const float* p = cb + (size_t)warp * DIM;
    float s = 0.f;
    #pragma unroll
    for (int i = 0; i < DIM/32; ++i) { float v = p[lane + i*32]; s = __fmaf_rn(v, v, s); }
    #pragma unroll
    for (int o = 16; o; o >>= 1) s += __shfl_xor_sync(0xffffffffu, s, o);
    if (lane == 0) g_esq[warp] = s;
}

// ---------------- rowsum: one warp per row (argmin is ulp-translation invariant, order free) --------
__global__ void rowsum_kernel() {
    int warp = (blockIdx.x * blockDim.x + threadIdx.x) >> 5;
    int lane = threadIdx.x & 31;
    if (warp >= NROWS) return;
    const float* p = g_resid + (size_t)warp * DIM;
    float s = 0.f;
    #pragma unroll
    for (int i = 0; i < DIM/32; ++i) { float v = p[lane + i*32]; s = __fmaf_rn(v, v, s); }
    #pragma unroll
    for (int o = 16; o; o >>= 1) s += __shfl_xor_sync(0xffffffffu, s, o);
    if (lane == 0) g_rowsum[warp] = s;
}

// ---------------- argmin: MT rows resident in smem, K split across blockIdx.y ----------------
__device__ __forceinline__ void sts_chunk(float* Bb, int tid, float4 v0, float4 v1) {
    // chunk layout: Bb[dd*KT + code], dd in [0,16)
    int lin0 = tid, lin1 = tid + 256;
    int code0 = lin0 >> 2, j0 = (lin0 & 3) * 4;
    int code1 = lin1 >> 2, j1 = (lin1 & 3) * 4;
    Bb[(j0+0)*KT + code0] = v0.x; Bb[(j0+1)*KT + code0] = v0.y;
    Bb[(j0+2)*KT + code0] = v0.z; Bb[(j0+3)*KT + code0] = v0.w;
    Bb[(j1+0)*KT + code1] = v1.x; Bb[(j1+1)*KT + code1] = v1.y;
    Bb[(j1+2)*KT + code1] = v1.z; Bb[(j1+3)*KT + code1] = v1.w;
}

__global__ __launch_bounds__(256, 1)
void argmin_kernel(const float* __restrict__ cb, int layer) {
    extern __shared__ float sm[];
    float* A_s = sm;                         // [MT][AST]
    float* B_s = sm + MT * AST;              // [2][DT][KT]
    int tid = threadIdx.x;
    int tx = tid & 15;                       // code group (8 codes)
    int ty = tid >> 4;                       // row group (4 rows)
    int rb = blockIdx.x * MT;
    int split = blockIdx.y;

    // Load A tile (rows resident for whole kernel)
    const float4* R4 = (const float4*)g_resid;
    #pragma unroll
    for (int it = 0; it < (MT * (DIM/4)) / 256; ++it) {
        int lin = tid + it * 256;
        int row = lin >> 7;                  // DIM/4 = 128 float4 per row
        int c4  = lin & 127;
        float4 v = R4[(size_t)(rb + row) * 128 + c4];
        ((float4*)(A_s + row * AST))[c4] = v;
    }
    float rs[4];
    #pragma unroll
    for (int i = 0; i < 4; ++i) rs[i] = g_rowsum[rb + ty*4 + i];
    __syncthreads();

    const float4* CB4 = (const float4*)cb + (size_t)layer * KC * (DIM/4);
    const float* esq = g_esq + layer * KC;

    unsigned long long best[4] = { ~0ULL, ~0ULL, ~0ULL, ~0ULL };

    for (int kt = 0; kt < NKT; ++kt) {
        int kb = split * KSPLIT + kt * KT;
        float acc[4][8];
        #pragma unroll
        for (int r = 0; r < 4; ++r)
            #pragma unroll
            for (int c = 0; c < 8; ++c) acc[r][c] = 0.f;

        // prologue: chunk 0 into buf 0
        {
            int lin0 = tid, lin1 = tid + 256;
            float4 v0 = CB4[(size_t)(kb + (lin0 >> 2)) * 128 + (lin0 & 3)];
            float4 v1 = CB4[(size_t)(kb + (lin1 >> 2)) * 128 + (lin1 & 3)];
            sts_chunk(B_s, tid, v0, v1);
        }
        __syncthreads();

        for (int dc = 0; dc < NCHUNK; ++dc) {
            int buf = dc & 1;
            float4 n0, n1;
            bool more = (dc + 1 < NCHUNK);
            if (more) {
                int cbase = (dc + 1) * 4;
                int lin0 = tid, lin1 = tid + 256;
                n0 = CB4[(size_t)(kb + (lin0 >> 2)) * 128 + cbase + (lin0 & 3)];
                n1 = CB4[(size_t)(kb + (lin1 >> 2)) * 128 + cbase + (lin1 & 3)];
            }
            const float* Bb = B_s + buf * (DT * KT);
            int dbase = dc * DT;
            #pragma unroll
            for (int dd = 0; dd < DT; ++dd) {
                float a[4];
                #pragma unroll
                for (int r = 0; r < 4; ++r) a[r] = A_s[(ty*4 + r) * AST + dbase + dd];
                float4 b0 = *(const float4*)(Bb + dd*KT + tx*8);
                float4 b1 = *(const float4*)(Bb + dd*KT + tx*8 + 4);
                float b[8] = { b0.x, b0.y, b0.z, b0.w, b1.x, b1.y, b1.z, b1.w };
                #pragma unroll
                for (int r = 0; r < 4; ++r)
                    #pragma unroll
                    for (int c = 0; c < 8; ++c)
                        acc[r][c] = __fmaf_rn(a[r], b[c], acc[r][c]);
            }
            if (more) sts_chunk(B_s + (buf ^ 1) * (DT * KT), tid, n0, n1);
            __syncthreads();
        }

        // Score with XLA's exact rounding structure:
        //   t = fl(rowsum + esq);  d = fl(t - 2*dot)  (FFMA single-rounding; 2*dot exact)
        float e8[8];
        #pragma unroll
        for (int c = 0; c < 8; ++c) e8[c] = esq[kb + tx*8 + c];
        #pragma unroll
        for (int c = 0; c < 8; ++c) {
            int code = kb + tx*8 + c;
            #pragma unroll
            for (int r = 0; r < 4; ++r) {
                float t = __fadd_rn(rs[r], e8[c]);
                float d = __fmaf_rn(acc[r][c], -2.0f, t);
                unsigned long long key = ((unsigned long long)__float_as_uint(d) << 32) | (unsigned)code;
                if (key < best[r]) best[r] = key;
            }
        }
    }

    // Reduce across the 16 code-group lanes (xor masks stay within the tx half)
    #pragma unroll
    for (int o = 8; o; o >>= 1) {
        #pragma unroll
        for (int r = 0; r < 4; ++r) {
            unsigned long long other = __shfl_xor_sync(0xffffffffu, best[r], o);
            if (other < best[r]) best[r] = other;
        }
    }
    if (tx == 0) {
        #pragma unroll
        for (int r = 0; r < 4; ++r)
            g_part[(size_t)(rb + ty*4 + r) * SPLITS + split] = best[r];
    }
}

// ---------------- combine split partials (u64 min preserves first-index tie-break) -------------
__global__ void combine_kernel() {
    int n = blockIdx.x * blockDim.x + threadIdx.x;
    if (n >= NROWS) return;
    unsigned long long b = ~0ULL;
    #pragma unroll
    for (int s = 0; s < SPLITS; ++s) {
        unsigned long long v = g_part[(size_t)n * SPLITS + s];
        if (v < b) b = v;
    }
    g_best[n] = (int)(b & 0xffffffffu);
}

// ---------------- update: gather, straight-through arithmetic, residual, loss, idx --------------
__global__ void update_kernel(const float* __restrict__ cb, float* __restrict__ outQ,
                              float* __restrict__ outIdx, int layer) {
    __shared__ float red[256];
    int tid = threadIdx.x;
    int sub = tid >> 7;                      // 2 rows per CTA
    int dt  = tid & 127;                     // 128 threads * float4 = 512
    int row = blockIdx.x * 2 + sub;
    int idx = g_best[row];

    const float4* q4p = (const float4*)(cb + ((size_t)layer * KC + (size_t)idx) * DIM);
    float4 q = q4p[dt];
    float4* Rr = ((float4*)g_resid) + (size_t)row * 128;
    float4 r = Rr[dt];

    // qmr = fl(q - r); qst = fl(r + qmr)  (matches JAX straight-through fp)
    float4 qmr, qst, o, nr;
    qmr.x = q.x - r.x; qmr.y = q.y - r.y; qmr.z = q.z - r.z; qmr.w = q.w - r.w;
    qst.x = r.x + qmr.x; qst.y = r.y + qmr.y; qst.z = r.z + qmr.z; qst.w = r.w + qmr.w;

    float4* Or = ((float4*)outQ) + (size_t)row * 128;
    o = Or[dt];
    o.x += qst.x; o.y += qst.y; o.z += qst.z; o.w += qst.w;
    Or[dt] = o;

    nr.x = r.x - qst.x; nr.y = r.y - qst.y; nr.z = r.z - qst.z; nr.w = r.w - qst.w;
    Rr[dt] = nr;

    float lp = qmr.x*qmr.x + qmr.y*qmr.y + qmr.z*qmr.z + qmr.w*qmr.w;
    red[tid] = lp;
    __syncthreads();
    #pragma unroll
    for (int s = 64; s; s >>= 1) {
        if (dt < s) red[sub*128 + dt] += red[sub*128 + dt + s];
        __syncthreads();
    }
    if (dt == 0) {
        g_rowloss[row] += red[sub*128];                   // one writer per row, layers sequential
        outIdx[(size_t)row * NL + layer] = (float)idx;
    }
}

// ---------------- deterministic loss finalize ----------------
__global__ void finalize_kernel(float* __restrict__ out) {
    __shared__ float red[256];
    int tid = threadIdx.x;
    float s = 0.f;
    for (int i = tid; i < NROWS; i += 256) s += g_rowloss[i];
    red[tid] = s;
    __syncthreads();
    #pragma unroll
    for (int st = 128; st; st >>= 1) {
        if (tid < st) red[tid] += red[tid + st];
        __syncthreads();
    }
    if (tid == 0)
        out[(size_t)NROWS * DIM] = COMMIT * red[0] * (1.0f / ((float)NROWS * (float)DIM));
}

// ---------------- launch ----------------
extern "C" void kernel_launch(void* const* d_in, const int* in_sizes, int n_in,
                              void* d_out, int out_size) {
    const float* x  = (const float*)d_in[0];   // [256,41,512]
    const float* cb = (const float*)d_in[1];   // [8,4096,512]
    float* out = (float*)d_out;
    float* outQ = out;                                         // [N,512]
    float* outIdx = out + (size_t)NROWS * DIM + 1;             // loss at [N*512], idx after

    cudaFuncSetAttribute(argmin_kernel, cudaFuncAttributeMaxDynamicSharedMemorySize, SMEM_BYTES);

    init_kernel<<<(NROWS * DIM / 4) / 256, 256>>>((const float4*)x, (float4*)outQ);
    esq_kernel<<<(NL * KC) / 8, 256>>>(cb);

    for (int l = 0; l < NL; ++l) {
        rowsum_kernel<<<NROWS / 8, 256>>>();
        argmin_kernel<<<dim3(NROWS / MT, SPLITS), 256, SMEM_BYTES>>>(cb, l);
        combine_kernel<<<(NROWS + 255) / 256, 256>>>();
        update_kernel<<<NROWS / 2, 256>>>(cb, outQ, outIdx, l);
    }
    finalize_kernel<<<1, 256>>>(out);
}